// round 10
// baseline (speedup 1.0000x reference)
#include <cuda_runtime.h>
#include <cuda_fp16.h>
#include <cstdint>

// Shapes fixed by the problem: M=1024, K=4096, N=4096, group size 128.
#define M_DIM 1024
#define K_DIM 4096
#define N_DIM 4096

// Scratch (__device__ global; cudaMalloc forbidden): x converted fp32 -> fp16.
__device__ __half g_X[(size_t)M_DIM * K_DIM];

// ===========================================================================
// helpers
// ===========================================================================
__device__ __forceinline__ uint32_t smem_u32(const void* p) {
    uint32_t a;
    asm("{ .reg .u64 t; cvta.to.shared.u64 t, %1; cvt.u32.u64 %0, t; }"
        : "=r"(a) : "l"(p));
    return a;
}
__device__ __forceinline__ void cp16(uint32_t dst, const __half* src) {
    size_t g = __cvta_generic_to_global((const void*)src);
    asm volatile("cp.async.cg.shared.global [%0], [%1], 16;\n" :: "r"(dst), "l"(g));
}
__device__ __forceinline__ void ldm_x4(uint32_t* r, uint32_t addr) {
    asm volatile("ldmatrix.sync.aligned.m8n8.x4.shared.b16 {%0,%1,%2,%3}, [%4];"
                 : "=r"(r[0]), "=r"(r[1]), "=r"(r[2]), "=r"(r[3]) : "r"(addr));
}
__device__ __forceinline__ void mma16816(float* d, const uint32_t* a,
                                         uint32_t b0, uint32_t b1) {
    asm volatile("mma.sync.aligned.m16n8k16.row.col.f32.f16.f16.f32 "
                 "{%0,%1,%2,%3}, {%4,%5,%6,%7}, {%8,%9}, {%0,%1,%2,%3};"
                 : "+f"(d[0]), "+f"(d[1]), "+f"(d[2]), "+f"(d[3])
                 : "r"(a[0]), "r"(a[1]), "r"(a[2]), "r"(a[3]), "r"(b0), "r"(b1));
}

// ===========================================================================
// Kernel 0: x fp32 -> fp16 (lossless; harness upcasts fp16 inputs to fp32).
// One uint4 (8 halfs) store per thread.
// ===========================================================================
__global__ void convert_x_kernel(const float* __restrict__ x, size_t n) {
    size_t i = ((size_t)blockIdx.x * blockDim.x + threadIdx.x) * 8;
    if (i >= n) return;
    float4 a = *(const float4*)&x[i];
    float4 b = *(const float4*)&x[i + 4];
    __half2 h0 = __floats2half2_rn(a.x, a.y);
    __half2 h1 = __floats2half2_rn(a.z, a.w);
    __half2 h2 = __floats2half2_rn(b.x, b.y);
    __half2 h3 = __floats2half2_rn(b.z, b.w);
    uint4 u;
    u.x = *(uint32_t*)&h0; u.y = *(uint32_t*)&h1;
    u.z = *(uint32_t*)&h2; u.w = *(uint32_t*)&h3;
    *(uint4*)&g_X[i] = u;
}

// ===========================================================================
// Kernel 1: fused GPTQ-dequant + GEMM + bias.
//   out[M][N] = x @ W + bias,  W[k][n] = (q - (z+1)) * scale[g][n]
// CTA tile 128M x 256N, BK=64, 3-stage SMEM ring, 256 threads (8 warps, 2x4),
// warp tile 64x64. B tile stored [n][k] (K-major rows of 128B): one qweight
// word = one contiguous 16B STS.128. ldmatrix non-trans on [n][k] gives the
// m16n8k16 B fragment directly.
// ===========================================================================
#define BM 128
#define BN 256
#define BKC 64
#define STAGES 3
#define ASTG (BM * BKC * 2)        // 16 KB
#define BSTG (BN * BKC * 2)        // 32 KB
#define STG  (ASTG + BSTG)         // 48 KB
#define SMEM_TOT (STAGES * STG)    // 144 KB

__global__ __launch_bounds__(256, 1)
void gemm_fused_kernel(const int* __restrict__ qw,
                       const float* __restrict__ scales,
                       const int* __restrict__ qz,
                       const int* __restrict__ gidx,
                       const float* __restrict__ bias,
                       float* __restrict__ out,
                       int M, int N, int K) {
    extern __shared__ char sm[];
    const int tid  = threadIdx.x;
    const int lane = tid & 31;
    const int warp = tid >> 5;
    const int wm   = (warp & 1) * 64;
    const int wn   = (warp >> 1) * 64;
    const int mb   = blockIdx.y * BM;
    const int nb   = blockIdx.x * BN;
    const uint32_t sbase = smem_u32(sm);

    float acc[4][8][4];
#pragma unroll
    for (int i = 0; i < 4; i++)
#pragma unroll
        for (int j = 0; j < 8; j++)
#pragma unroll
            for (int c = 0; c < 4; c++) acc[i][j][c] = 0.0f;

    const int NKC = K / BKC;          // 64
    const int n_g = nb + tid;         // this thread's weight column

    // ---- fetch qweight words + scale/zero for one k-chunk into regs ----
    auto fetchB = [&](int kc, uint32_t* w, float& s, float& z1) {
        int k0 = kc * BKC;
        int g  = gidx[k0];
        s = scales[(size_t)g * N + n_g];
        unsigned zw = (unsigned)qz[(size_t)g * (N >> 3) + (n_g >> 3)];
        z1 = (float)((zw >> ((n_g & 7) * 4)) & 15u) + 1.0f;
        int kp0 = k0 >> 3;
#pragma unroll
        for (int t = 0; t < 8; t++)
            w[t] = (uint32_t)qw[(size_t)(kp0 + t) * N + n_g];
    };

    // ---- dequant regs -> B stage buffer ([n][k], SW128 chunk XOR) ----
    auto stsB = [&](int st, const uint32_t* w, float s, float z1) {
        char* rowp = sm + st * STG + ASTG + tid * 128;
        int r7 = tid & 7;
#pragma unroll
        for (int kp = 0; kp < 8; kp++) {
            uint32_t q = w[kp];
            __half2 h0 = __floats2half2_rn(((float)(q         & 15u) - z1) * s,
                                           ((float)((q >> 4)  & 15u) - z1) * s);
            __half2 h1 = __floats2half2_rn(((float)((q >> 8)  & 15u) - z1) * s,
                                           ((float)((q >> 12) & 15u) - z1) * s);
            __half2 h2 = __floats2half2_rn(((float)((q >> 16) & 15u) - z1) * s,
                                           ((float)((q >> 20) & 15u) - z1) * s);
            __half2 h3 = __floats2half2_rn(((float)((q >> 24) & 15u) - z1) * s,
                                           ((float)((q >> 28) & 15u) - z1) * s);
            uint4 u;
            u.x = *(uint32_t*)&h0; u.y = *(uint32_t*)&h1;
            u.z = *(uint32_t*)&h2; u.w = *(uint32_t*)&h3;
            *(uint4*)(rowp + ((kp ^ r7) * 16)) = u;
        }
    };

    // ---- A stage loader: 128 rows x 128B via cp.async ----
    auto cpA = [&](int st, int kc) {
        int k0 = kc * BKC;
        uint32_t sa = sbase + st * STG;
#pragma unroll
        for (int t = 0; t < 4; t++) {
            int idx = t * 256 + tid;
            int r = idx >> 3, c = idx & 7;
            cp16(sa + r * 128 + ((c ^ (r & 7)) * 16),
                 g_X + (size_t)(mb + r) * K + k0 + c * 8);
        }
    };

    // ---- prologue ----
    uint32_t wq[2][8];
    float ws[2], wz[2];
    fetchB(0, wq[0], ws[0], wz[0]);
    stsB(0, wq[0], ws[0], wz[0]);
    cpA(0, 0);
    asm volatile("cp.async.commit_group;\n" ::: "memory");
    fetchB(1, wq[1], ws[1], wz[1]);
    stsB(1, wq[1], ws[1], wz[1]);
    cpA(1, 1);
    asm volatile("cp.async.commit_group;\n" ::: "memory");
    fetchB(2, wq[0], ws[0], wz[0]);       // stage 2's regs, consumed at iter 0
    asm volatile("cp.async.wait_group 1;\n" ::: "memory");
    __syncthreads();                      // stage 0 fully resident

    // ---- mainloop ----
    for (int kc = 0; kc < NKC; kc++) {
        const int cur = kc % 3;
        const int pb  = kc & 1;           // reg buffer holding stage kc+2

        if (kc + 3 < NKC)
            fetchB(kc + 3, wq[pb ^ 1], ws[pb ^ 1], wz[pb ^ 1]);

        const uint32_t sa = sbase + cur * STG;
        const uint32_t sb = sa + ASTG;
#pragma unroll
        for (int kk = 0; kk < 4; kk++) {
            uint32_t a[4][4];
#pragma unroll
            for (int mi = 0; mi < 4; mi++) {
                int row = wm + mi * 16 + (lane & 15);
                int c   = kk * 2 + (lane >> 4);
                ldm_x4(a[mi], sa + row * 128 + ((c ^ (row & 7)) * 16));
            }
#pragma unroll
            for (int ni = 0; ni < 4; ni++) {
                uint32_t b[4];
                int row = wn + ni * 16 + ((lane >> 4) * 8) + (lane & 7);
                int c   = kk * 2 + ((lane >> 3) & 1);
                ldm_x4(b, sb + row * 128 + ((c ^ (row & 7)) * 16));
#pragma unroll
                for (int mi = 0; mi < 4; mi++) {
                    mma16816(acc[mi][2 * ni],     a[mi], b[0], b[1]);
                    mma16816(acc[mi][2 * ni + 1], a[mi], b[2], b[3]);
                }
            }
        }

        if (kc + 2 < NKC) {
            int st = (kc + 2) % 3;        // == (kc-1)%3, freed by last barrier
            stsB(st, wq[pb], ws[pb], wz[pb]);
            cpA(st, kc + 2);
        }
        asm volatile("cp.async.commit_group;\n" ::: "memory");
        asm volatile("cp.async.wait_group 1;\n" ::: "memory");
        __syncthreads();
    }

    // ---- epilogue: + bias, fp32 out ----
    const int gq = lane >> 2, tq = lane & 3;
#pragma unroll
    for (int mi = 0; mi < 4; mi++) {
        int row0 = mb + wm + mi * 16 + gq;
#pragma unroll
        for (int ng = 0; ng < 8; ng++) {
            int col = nb + wn + ng * 8 + tq * 2;
            float b0 = bias[col];
            float b1 = bias[col + 1];
            float2 v0 = make_float2(acc[mi][ng][0] + b0, acc[mi][ng][1] + b1);
            float2 v1 = make_float2(acc[mi][ng][2] + b0, acc[mi][ng][3] + b1);
            *(float2*)&out[(size_t)row0 * N + col]       = v0;
            *(float2*)&out[(size_t)(row0 + 8) * N + col] = v1;
        }
    }
}

// ===========================================================================
// Launch: inputs in metadata order: x, qweight, scales, qzeros, g_idx, bias
// (fp16 tensors arrive upcast to float32)
// ===========================================================================
extern "C" void kernel_launch(void* const* d_in, const int* in_sizes, int n_in,
                              void* d_out, int out_size) {
    const float* x       = (const float*)d_in[0];
    const int*   qweight = (const int*)d_in[1];
    const float* scales  = (const float*)d_in[2];
    const int*   qzeros  = (const int*)d_in[3];
    const int*   g_idx   = (const int*)d_in[4];
    const float* bias    = (const float*)d_in[5];
    float*       out     = (float*)d_out;

    const int K = in_sizes[4];          // g_idx length
    const int N = in_sizes[5];          // bias length
    const int M = in_sizes[0] / K;      // x is [M, K]

    // 0) x fp32 -> fp16
    size_t nx = (size_t)M * K;
    convert_x_kernel<<<(unsigned)((nx / 8 + 255) / 256), 256>>>(x, nx);

    // 1) fused dequant + GEMM + bias (16 x 8 = 128 CTAs, one wave)
    static bool attr_set = false;
    if (!attr_set) {
        cudaFuncSetAttribute(gemm_fused_kernel,
                             cudaFuncAttributeMaxDynamicSharedMemorySize, SMEM_TOT);
        attr_set = true;
    }
    dim3 gg(N / BN, M / BM);
    gemm_fused_kernel<<<gg, 256, SMEM_TOT>>>(qweight, scales, qzeros, g_idx,
                                             bias, out, M, N, K);
}

// round 11
// speedup vs baseline: 1.0081x; 1.0081x over previous
#include <cuda_runtime.h>
#include <cuda_fp16.h>
#include <cstdint>

// Shapes fixed by the problem: M=1024, K=4096, N=4096, group size 128.
#define M_DIM 1024
#define K_DIM 4096
#define N_DIM 4096

// Scratch (__device__ global; cudaMalloc forbidden): x converted fp32 -> fp16.
__device__ __half g_X[(size_t)M_DIM * K_DIM];

// ===========================================================================
// helpers
// ===========================================================================
__device__ __forceinline__ uint32_t smem_u32(const void* p) {
    uint32_t a;
    asm("{ .reg .u64 t; cvta.to.shared.u64 t, %1; cvt.u32.u64 %0, t; }"
        : "=r"(a) : "l"(p));
    return a;
}
__device__ __forceinline__ void cp16(uint32_t dst, const __half* src) {
    size_t g = __cvta_generic_to_global((const void*)src);
    asm volatile("cp.async.cg.shared.global [%0], [%1], 16;\n" :: "r"(dst), "l"(g));
}
__device__ __forceinline__ void ldm_x4(uint32_t* r, uint32_t addr) {
    asm volatile("ldmatrix.sync.aligned.m8n8.x4.shared.b16 {%0,%1,%2,%3}, [%4];"
                 : "=r"(r[0]), "=r"(r[1]), "=r"(r[2]), "=r"(r[3]) : "r"(addr));
}
__device__ __forceinline__ void mma16816(float* d, const uint32_t* a,
                                         uint32_t b0, uint32_t b1) {
    asm volatile("mma.sync.aligned.m16n8k16.row.col.f32.f16.f16.f32 "
                 "{%0,%1,%2,%3}, {%4,%5,%6,%7}, {%8,%9}, {%0,%1,%2,%3};"
                 : "+f"(d[0]), "+f"(d[1]), "+f"(d[2]), "+f"(d[3])
                 : "r"(a[0]), "r"(a[1]), "r"(a[2]), "r"(a[3]), "r"(b0), "r"(b1));
}

// ===========================================================================
// Kernel 0: x fp32 -> fp16 (lossless; harness upcasts fp16 inputs to fp32).
// One uint4 (8 halfs) store per thread.
// ===========================================================================
__global__ void convert_x_kernel(const float* __restrict__ x, size_t n) {
    size_t i = ((size_t)blockIdx.x * blockDim.x + threadIdx.x) * 8;
    if (i >= n) return;
    float4 a = *(const float4*)&x[i];
    float4 b = *(const float4*)&x[i + 4];
    __half2 h0 = __floats2half2_rn(a.x, a.y);
    __half2 h1 = __floats2half2_rn(a.z, a.w);
    __half2 h2 = __floats2half2_rn(b.x, b.y);
    __half2 h3 = __floats2half2_rn(b.z, b.w);
    uint4 u;
    u.x = *(uint32_t*)&h0; u.y = *(uint32_t*)&h1;
    u.z = *(uint32_t*)&h2; u.w = *(uint32_t*)&h3;
    *(uint4*)&g_X[i] = u;
}

// ===========================================================================
// Kernel 1: fused GPTQ-dequant + GEMM + bias.
//   out[M][N] = x @ W + bias,  W[k][n] = (q - (z+1)) * scale[g][n]
// CTA tile 128M x 256N, BK=64, 3-stage SMEM ring, 256 threads (8 warps, 2x4),
// warp tile 64x64. B tile stored [n][k] (K-major rows of 128B): one qweight
// word = one contiguous 16B STS.128. ldmatrix non-trans on [n][k] gives the
// m16n8k16 B fragment directly.
// ===========================================================================
#define BM 128
#define BN 256
#define BKC 64
#define STAGES 3
#define ASTG (BM * BKC * 2)        // 16 KB
#define BSTG (BN * BKC * 2)        // 32 KB
#define STG  (ASTG + BSTG)         // 48 KB
#define SMEM_TOT (STAGES * STG)    // 144 KB

__global__ __launch_bounds__(256, 1)
void gemm_fused_kernel(const int* __restrict__ qw,
                       const float* __restrict__ scales,
                       const int* __restrict__ qz,
                       const int* __restrict__ gidx,
                       const float* __restrict__ bias,
                       float* __restrict__ out,
                       int M, int N, int K) {
    extern __shared__ char sm[];
    const int tid  = threadIdx.x;
    const int lane = tid & 31;
    const int warp = tid >> 5;
    const int wm   = (warp & 1) * 64;
    const int wn   = (warp >> 1) * 64;
    const int mb   = blockIdx.y * BM;
    const int nb   = blockIdx.x * BN;
    const uint32_t sbase = smem_u32(sm);

    float acc[4][8][4];
#pragma unroll
    for (int i = 0; i < 4; i++)
#pragma unroll
        for (int j = 0; j < 8; j++)
#pragma unroll
            for (int c = 0; c < 4; c++) acc[i][j][c] = 0.0f;

    const int NKC = K / BKC;          // 64
    const int n_g = nb + tid;         // this thread's weight column

    // ---- fetch qweight words + scale/zero for one k-chunk into regs ----
    auto fetchB = [&](int kc, uint32_t* w, float& s, float& z1) {
        int k0 = kc * BKC;
        int g  = gidx[k0];
        s = scales[(size_t)g * N + n_g];
        unsigned zw = (unsigned)qz[(size_t)g * (N >> 3) + (n_g >> 3)];
        z1 = (float)((zw >> ((n_g & 7) * 4)) & 15u) + 1.0f;
        int kp0 = k0 >> 3;
#pragma unroll
        for (int t = 0; t < 8; t++)
            w[t] = (uint32_t)qw[(size_t)(kp0 + t) * N + n_g];
    };

    // ---- dequant regs -> B stage buffer ([n][k], SW128 chunk XOR) ----
    auto stsB = [&](int st, const uint32_t* w, float s, float z1) {
        char* rowp = sm + st * STG + ASTG + tid * 128;
        int r7 = tid & 7;
#pragma unroll
        for (int kp = 0; kp < 8; kp++) {
            uint32_t q = w[kp];
            __half2 h0 = __floats2half2_rn(((float)(q         & 15u) - z1) * s,
                                           ((float)((q >> 4)  & 15u) - z1) * s);
            __half2 h1 = __floats2half2_rn(((float)((q >> 8)  & 15u) - z1) * s,
                                           ((float)((q >> 12) & 15u) - z1) * s);
            __half2 h2 = __floats2half2_rn(((float)((q >> 16) & 15u) - z1) * s,
                                           ((float)((q >> 20) & 15u) - z1) * s);
            __half2 h3 = __floats2half2_rn(((float)((q >> 24) & 15u) - z1) * s,
                                           ((float)((q >> 28) & 15u) - z1) * s);
            uint4 u;
            u.x = *(uint32_t*)&h0; u.y = *(uint32_t*)&h1;
            u.z = *(uint32_t*)&h2; u.w = *(uint32_t*)&h3;
            *(uint4*)(rowp + ((kp ^ r7) * 16)) = u;
        }
    };

    // ---- A stage loader: 128 rows x 128B via cp.async ----
    auto cpA = [&](int st, int kc) {
        int k0 = kc * BKC;
        uint32_t sa = sbase + st * STG;
#pragma unroll
        for (int t = 0; t < 4; t++) {
            int idx = t * 256 + tid;
            int r = idx >> 3, c = idx & 7;
            cp16(sa + r * 128 + ((c ^ (r & 7)) * 16),
                 g_X + (size_t)(mb + r) * K + k0 + c * 8);
        }
    };

    // ---- prologue ----
    uint32_t wq[2][8];
    float ws[2], wz[2];
    fetchB(0, wq[0], ws[0], wz[0]);
    stsB(0, wq[0], ws[0], wz[0]);
    cpA(0, 0);
    asm volatile("cp.async.commit_group;\n" ::: "memory");
    fetchB(1, wq[1], ws[1], wz[1]);
    stsB(1, wq[1], ws[1], wz[1]);
    cpA(1, 1);
    asm volatile("cp.async.commit_group;\n" ::: "memory");
    fetchB(2, wq[0], ws[0], wz[0]);       // stage 2's regs, consumed at iter 0
    asm volatile("cp.async.wait_group 1;\n" ::: "memory");
    __syncthreads();                      // stage 0 fully resident

    // ---- mainloop ----
    for (int kc = 0; kc < NKC; kc++) {
        const int cur = kc % 3;
        const int pb  = kc & 1;           // reg buffer holding stage kc+2

        if (kc + 3 < NKC)
            fetchB(kc + 3, wq[pb ^ 1], ws[pb ^ 1], wz[pb ^ 1]);

        const uint32_t sa = sbase + cur * STG;
        const uint32_t sb = sa + ASTG;
#pragma unroll
        for (int kk = 0; kk < 4; kk++) {
            uint32_t a[4][4];
#pragma unroll
            for (int mi = 0; mi < 4; mi++) {
                int row = wm + mi * 16 + (lane & 15);
                int c   = kk * 2 + (lane >> 4);
                ldm_x4(a[mi], sa + row * 128 + ((c ^ (row & 7)) * 16));
            }
#pragma unroll
            for (int ni = 0; ni < 4; ni++) {
                uint32_t b[4];
                int row = wn + ni * 16 + ((lane >> 4) * 8) + (lane & 7);
                int c   = kk * 2 + ((lane >> 3) & 1);
                ldm_x4(b, sb + row * 128 + ((c ^ (row & 7)) * 16));
#pragma unroll
                for (int mi = 0; mi < 4; mi++) {
                    mma16816(acc[mi][2 * ni],     a[mi], b[0], b[1]);
                    mma16816(acc[mi][2 * ni + 1], a[mi], b[2], b[3]);
                }
            }
        }

        if (kc + 2 < NKC) {
            int st = (kc + 2) % 3;        // == (kc-1)%3, freed by last barrier
            stsB(st, wq[pb], ws[pb], wz[pb]);
            cpA(st, kc + 2);
        }
        asm volatile("cp.async.commit_group;\n" ::: "memory");
        asm volatile("cp.async.wait_group 1;\n" ::: "memory");
        __syncthreads();
    }

    // ---- epilogue: + bias, fp32 out ----
    const int gq = lane >> 2, tq = lane & 3;
#pragma unroll
    for (int mi = 0; mi < 4; mi++) {
        int row0 = mb + wm + mi * 16 + gq;
#pragma unroll
        for (int ng = 0; ng < 8; ng++) {
            int col = nb + wn + ng * 8 + tq * 2;
            float b0 = bias[col];
            float b1 = bias[col + 1];
            float2 v0 = make_float2(acc[mi][ng][0] + b0, acc[mi][ng][1] + b1);
            float2 v1 = make_float2(acc[mi][ng][2] + b0, acc[mi][ng][3] + b1);
            *(float2*)&out[(size_t)row0 * N + col]       = v0;
            *(float2*)&out[(size_t)(row0 + 8) * N + col] = v1;
        }
    }
}

// ===========================================================================
// Launch: inputs in metadata order: x, qweight, scales, qzeros, g_idx, bias
// (fp16 tensors arrive upcast to float32)
// ===========================================================================
extern "C" void kernel_launch(void* const* d_in, const int* in_sizes, int n_in,
                              void* d_out, int out_size) {
    const float* x       = (const float*)d_in[0];
    const int*   qweight = (const int*)d_in[1];
    const float* scales  = (const float*)d_in[2];
    const int*   qzeros  = (const int*)d_in[3];
    const int*   g_idx   = (const int*)d_in[4];
    const float* bias    = (const float*)d_in[5];
    float*       out     = (float*)d_out;

    const int K = in_sizes[4];          // g_idx length
    const int N = in_sizes[5];          // bias length
    const int M = in_sizes[0] / K;      // x is [M, K]

    // 0) x fp32 -> fp16
    size_t nx = (size_t)M * K;
    convert_x_kernel<<<(unsigned)((nx / 8 + 255) / 256), 256>>>(x, nx);

    // 1) fused dequant + GEMM + bias (16 x 8 = 128 CTAs, one wave)
    static bool attr_set = false;
    if (!attr_set) {
        cudaFuncSetAttribute(gemm_fused_kernel,
                             cudaFuncAttributeMaxDynamicSharedMemorySize, SMEM_TOT);
        attr_set = true;
    }
    dim3 gg(N / BN, M / BM);
    gemm_fused_kernel<<<gg, 256, SMEM_TOT>>>(qweight, scales, qzeros, g_idx,
                                             bias, out, M, N, K);
}

// round 12
// speedup vs baseline: 1.1502x; 1.1409x over previous
#include <cuda_runtime.h>
#include <cuda_fp16.h>
#include <cstdint>

// Shapes fixed by the problem: M=1024, K=4096, N=4096, group size 128.
#define M_DIM 1024
#define K_DIM 4096
#define N_DIM 4096

// Scratch (__device__ global; cudaMalloc forbidden): x converted fp32 -> fp16.
__device__ __half g_X[(size_t)M_DIM * K_DIM];

// ===========================================================================
// helpers
// ===========================================================================
__device__ __forceinline__ uint32_t smem_u32(const void* p) {
    uint32_t a;
    asm("{ .reg .u64 t; cvta.to.shared.u64 t, %1; cvt.u32.u64 %0, t; }"
        : "=r"(a) : "l"(p));
    return a;
}
__device__ __forceinline__ void cp16(uint32_t dst, const __half* src) {
    size_t g = __cvta_generic_to_global((const void*)src);
    asm volatile("cp.async.cg.shared.global [%0], [%1], 16;\n" :: "r"(dst), "l"(g));
}
__device__ __forceinline__ void ldm_x4(uint32_t* r, uint32_t addr) {
    asm volatile("ldmatrix.sync.aligned.m8n8.x4.shared.b16 {%0,%1,%2,%3}, [%4];"
                 : "=r"(r[0]), "=r"(r[1]), "=r"(r[2]), "=r"(r[3]) : "r"(addr));
}
__device__ __forceinline__ void mma16816(float* d, const uint32_t* a,
                                         uint32_t b0, uint32_t b1) {
    asm volatile("mma.sync.aligned.m16n8k16.row.col.f32.f16.f16.f32 "
                 "{%0,%1,%2,%3}, {%4,%5,%6,%7}, {%8,%9}, {%0,%1,%2,%3};"
                 : "+f"(d[0]), "+f"(d[1]), "+f"(d[2]), "+f"(d[3])
                 : "r"(a[0]), "r"(a[1]), "r"(a[2]), "r"(a[3]), "r"(b0), "r"(b1));
}

// ===========================================================================
// Kernel 0: x fp32 -> fp16 (lossless; harness upcasts fp16 inputs to fp32).
// ===========================================================================
__global__ void convert_x_kernel(const float* __restrict__ x, size_t n) {
    size_t i = ((size_t)blockIdx.x * blockDim.x + threadIdx.x) * 8;
    if (i >= n) return;
    float4 a = *(const float4*)&x[i];
    float4 b = *(const float4*)&x[i + 4];
    __half2 h0 = __floats2half2_rn(a.x, a.y);
    __half2 h1 = __floats2half2_rn(a.z, a.w);
    __half2 h2 = __floats2half2_rn(b.x, b.y);
    __half2 h3 = __floats2half2_rn(b.z, b.w);
    uint4 u;
    u.x = *(uint32_t*)&h0; u.y = *(uint32_t*)&h1;
    u.z = *(uint32_t*)&h2; u.w = *(uint32_t*)&h3;
    *(uint4*)&g_X[i] = u;
}

// ===========================================================================
// Kernel 1: fused GPTQ-dequant + GEMM + bias.
//   out[M][N] = x @ W + bias,  W[k][n] = (q - (z+1)) * scale[g][n]
// CTA 128M x 256N, BK=64, 3-stage ring, 512 threads (16 warps, 2m x 8n),
// warp tile 64x32. B stored [n][k] K-major 128B rows (XOR-swizzled); dequant
// via fp16 magic-number trick (no I2F): h=(v|0x6400)==1024+v; w=(h-(1025+z))*s.
// ===========================================================================
#define BM 128
#define BN 256
#define BKC 64
#define STAGES 3
#define ASTG (BM * BKC * 2)        // 16 KB
#define BSTG (BN * BKC * 2)        // 32 KB
#define STG  (ASTG + BSTG)         // 48 KB
#define SMEM_TOT (STAGES * STG)    // 144 KB

__global__ __launch_bounds__(512, 1)
void gemm_fused_kernel(const int* __restrict__ qw,
                       const float* __restrict__ scales,
                       const int* __restrict__ qz,
                       const int* __restrict__ gidx,
                       const float* __restrict__ bias,
                       float* __restrict__ out,
                       int M, int N, int K) {
    extern __shared__ char sm[];
    const int tid  = threadIdx.x;
    const int lane = tid & 31;
    const int warp = tid >> 5;
    const int wm   = (warp & 1) * 64;     // 2 warps along M
    const int wn   = (warp >> 1) * 32;    // 8 warps along N
    const int mb   = blockIdx.y * BM;
    const int nb   = blockIdx.x * BN;
    const uint32_t sbase = smem_u32(sm);

    float acc[4][4][4];
#pragma unroll
    for (int i = 0; i < 4; i++)
#pragma unroll
        for (int j = 0; j < 4; j++)
#pragma unroll
            for (int c = 0; c < 4; c++) acc[i][j][c] = 0.0f;

    const int NKC = K / BKC;              // 64
    // dequant ownership: thread t -> column n = nb + (t&255), k-half = t>>8
    const int ncol  = tid & 255;
    const int khalf = tid >> 8;           // 0 or 1 (words 0-3 / 4-7 of chunk)
    const int n_g   = nb + ncol;

    // ---- fetch qweight words + scale/zero for one k-chunk into regs ----
    uint32_t wq[4];
    __half2  s2, off2;
    auto fetchB = [&](int kc) {
        int k0 = kc * BKC;
        int g  = gidx[k0];                // GS=128 >= BKC: uniform per chunk
        float sf = scales[(size_t)g * N + n_g];
        unsigned zw = (unsigned)qz[(size_t)g * (N >> 3) + (n_g >> 3)];
        int z = (int)((zw >> ((n_g & 7) * 4)) & 15u);
        s2   = __half2half2(__float2half(sf));
        off2 = __half2half2(__float2half((float)(1025 + z)));
        int kp0 = (k0 >> 3) + khalf * 4;
#pragma unroll
        for (int j = 0; j < 4; j++)
            wq[j] = (uint32_t)qw[(size_t)(kp0 + j) * N + n_g];
    };

    // ---- dequant regs -> B stage buffer ([n][k], chunk-XOR swizzle) ----
    auto stsB = [&](int st) {
        char* rowp = sm + st * STG + ASTG + (size_t)ncol * 128;
        const int r7 = ncol & 7;
#pragma unroll
        for (int j = 0; j < 4; j++) {
            uint32_t q = wq[j];
            int kp = khalf * 4 + j;
            uint4 u;
#pragma unroll
            for (int p = 0; p < 4; p++) {         // pairs (v2p, v2p+1)
                uint32_t lo = (q >> (8 * p))     & 0xFu;
                uint32_t hi = (q >> (8 * p + 4)) & 0xFu;
                uint32_t hb = lo | (hi << 16) | 0x64006400u;
                __half2 hv = *(__half2*)&hb;
                __half2 w  = __hmul2(__hsub2(hv, off2), s2);
                ((uint32_t*)&u)[p] = *(uint32_t*)&w;
            }
            *(uint4*)(rowp + ((kp ^ r7) * 16)) = u;
        }
    };

    // ---- A stage loader: 128 rows x 128B via cp.async ----
    auto cpA = [&](int st, int kc) {
        int k0 = kc * BKC;
        uint32_t sa = sbase + st * STG;
#pragma unroll
        for (int t = 0; t < 2; t++) {
            int idx = t * 512 + tid;
            int r = idx >> 3, c = idx & 7;
            cp16(sa + r * 128 + ((c ^ (r & 7)) * 16),
                 g_X + (size_t)(mb + r) * K + k0 + c * 8);
        }
    };

    // ---- prologue: stages 0 and 1 ----
    fetchB(0); stsB(0); cpA(0, 0);
    asm volatile("cp.async.commit_group;\n" ::: "memory");
    fetchB(1); stsB(1); cpA(1, 1);
    asm volatile("cp.async.commit_group;\n" ::: "memory");
    asm volatile("cp.async.wait_group 1;\n" ::: "memory");
    __syncthreads();                      // stage 0 resident

    // ---- mainloop ----
    for (int kc = 0; kc < NKC; kc++) {
        const int cur = kc % 3;
        if (kc + 2 < NKC) fetchB(kc + 2);     // LDG latency hides under MMAs

        const uint32_t sa = sbase + cur * STG;
        const uint32_t sb = sa + ASTG;
#pragma unroll
        for (int kk = 0; kk < 4; kk++) {
            uint32_t a[4][4];
#pragma unroll
            for (int mi = 0; mi < 4; mi++) {
                int row = wm + mi * 16 + (lane & 15);
                int c   = kk * 2 + (lane >> 4);
                ldm_x4(a[mi], sa + row * 128 + ((c ^ (row & 7)) * 16));
            }
#pragma unroll
            for (int ni = 0; ni < 2; ni++) {
                uint32_t b[4];
                int row = wn + ni * 16 + ((lane >> 4) * 8) + (lane & 7);
                int c   = kk * 2 + ((lane >> 3) & 1);
                ldm_x4(b, sb + row * 128 + ((c ^ (row & 7)) * 16));
#pragma unroll
                for (int mi = 0; mi < 4; mi++) {
                    mma16816(acc[mi][2 * ni],     a[mi], b[0], b[1]);
                    mma16816(acc[mi][2 * ni + 1], a[mi], b[2], b[3]);
                }
            }
        }

        if (kc + 2 < NKC) {
            int st = (kc + 2) % 3;        // == (kc-1)%3: freed by last barrier
            stsB(st);
            cpA(st, kc + 2);
        }
        asm volatile("cp.async.commit_group;\n" ::: "memory");
        asm volatile("cp.async.wait_group 1;\n" ::: "memory");  // stage kc+1 A done
        __syncthreads();
    }

    // ---- epilogue: + bias, fp32 out ----
    const int gq = lane >> 2, tq = lane & 3;
#pragma unroll
    for (int mi = 0; mi < 4; mi++) {
        int row0 = mb + wm + mi * 16 + gq;
#pragma unroll
        for (int ng = 0; ng < 4; ng++) {
            int col = nb + wn + ng * 8 + tq * 2;
            float b0 = bias[col];
            float b1 = bias[col + 1];
            float2 v0 = make_float2(acc[mi][ng][0] + b0, acc[mi][ng][1] + b1);
            float2 v1 = make_float2(acc[mi][ng][2] + b0, acc[mi][ng][3] + b1);
            *(float2*)&out[(size_t)row0 * N + col]       = v0;
            *(float2*)&out[(size_t)(row0 + 8) * N + col] = v1;
        }
    }
}

// ===========================================================================
// Launch: inputs in metadata order: x, qweight, scales, qzeros, g_idx, bias
// (fp16 tensors arrive upcast to float32)
// ===========================================================================
extern "C" void kernel_launch(void* const* d_in, const int* in_sizes, int n_in,
                              void* d_out, int out_size) {
    const float* x       = (const float*)d_in[0];
    const int*   qweight = (const int*)d_in[1];
    const float* scales  = (const float*)d_in[2];
    const int*   qzeros  = (const int*)d_in[3];
    const int*   g_idx   = (const int*)d_in[4];
    const float* bias    = (const float*)d_in[5];
    float*       out     = (float*)d_out;

    const int K = in_sizes[4];          // g_idx length
    const int N = in_sizes[5];          // bias length
    const int M = in_sizes[0] / K;      // x is [M, K]

    // 0) x fp32 -> fp16
    size_t nx = (size_t)M * K;
    convert_x_kernel<<<(unsigned)((nx / 8 + 255) / 256), 256>>>(x, nx);

    // 1) fused dequant + GEMM + bias (16 x 8 = 128 CTAs, one wave)
    static bool attr_set = false;
    if (!attr_set) {
        cudaFuncSetAttribute(gemm_fused_kernel,
                             cudaFuncAttributeMaxDynamicSharedMemorySize, SMEM_TOT);
        attr_set = true;
    }
    dim3 gg(N / BN, M / BM);
    gemm_fused_kernel<<<gg, 512, SMEM_TOT>>>(qweight, scales, qzeros, g_idx,
                                             bias, out, M, N, K);
}